// round 2
// baseline (speedup 1.0000x reference)
#include <cuda_runtime.h>
#include <math.h>

#define NE 2048
#define NX 3
#define NITER 10

// Scratch (allocation-free): all __device__ globals.
__device__ float g_s[NX][NE];        // static RHS (SC + last-column terms)
__device__ float g_Binv[NX*NX][NE];  // per-bin 3x3 inverse of B_i
__device__ float g_c[NE];            // c_j = dy*E_j
__device__ float g_F[2][NX][NE];     // double-buffered solution
__device__ float g_wF[2][NX][NE];    // double-buffered c_j*F_j (col NE-1 forced 0)

__device__ __forceinline__ float4 ld4(const float* __restrict__ p, int j) {
    return *reinterpret_cast<const float4*>(p + j);
}

// ---------------------------------------------------------------------------
// Setup: dy, src_last, F[:,NE-1], c_j, B_i^{-1}, s, initial guess F0 = Binv*s
// ---------------------------------------------------------------------------
__global__ __launch_bounds__(256) void setup_kernel(
    const float* __restrict__ E, const float* __restrict__ R,
    const float* __restrict__ K, const float* __restrict__ S0,
    const float* __restrict__ SC)
{
    int i = blockIdx.x * blockDim.x + threadIdx.x;
    if (i >= NE) return;

    const float dy = logf(E[NE-1] / E[0]) / (float)(NE - 1);

    float srcl[NX];
#pragma unroll
    for (int p = 0; p < NX; p++) srcl[p] = S0[p] / R[p*NE + NE-1];

    // F[:, NE-1] = FX_E0 (needed by everyone; cheap broadcast loads)
    float Flast[NX];
#pragma unroll
    for (int x = 0; x < NX; x++) {
        float acc = SC[x*NE + NE-1];
#pragma unroll
        for (int p = 0; p < NX; p++)
            acc += K[((size_t)((x*NX + p)*NE + (NE-1)))*NE + (NE-1)] * srcl[p];
        Flast[x] = acc / R[x*NE + NE-1];
    }

    if (i == NE-1) {
        g_c[NE-1] = dy * E[NE-1];
#pragma unroll
        for (int x = 0; x < NX; x++) {
            g_F[0][x][NE-1] = Flast[x];
            g_F[1][x][NE-1] = Flast[x];
            g_wF[0][x][NE-1] = 0.0f;   // j=NE-1 handled inside s, never in matvec
            g_wF[1][x][NE-1] = 0.0f;
        }
        return;
    }

    const float ci = dy * E[i];
    g_c[i] = ci;
    const float w_last = 0.5f * dy * E[NE-1];

    float Bm[3][3];
    float sv[NX];
#pragma unroll
    for (int x = 0; x < NX; x++) {
        float acc = SC[x*NE + i];
#pragma unroll
        for (int p = 0; p < NX; p++) {
            size_t rb = ((size_t)((x*NX + p)*NE + i)) * NE;
            float Kii = K[rb + i];
            float Kil = K[rb + NE-1];
            Bm[x][p] = -0.5f * ci * Kii + ((x == p) ? R[x*NE + i] : 0.0f);
            acc += Kil * (w_last * Flast[p] + srcl[p]);
        }
        sv[x] = acc;
    }

    // 3x3 inverse (adjugate / det); B ~ diag(R) dominant -> well-conditioned
    float c00 = Bm[1][1]*Bm[2][2] - Bm[1][2]*Bm[2][1];
    float c01 = Bm[1][2]*Bm[2][0] - Bm[1][0]*Bm[2][2];
    float c02 = Bm[1][0]*Bm[2][1] - Bm[1][1]*Bm[2][0];
    float det = Bm[0][0]*c00 + Bm[0][1]*c01 + Bm[0][2]*c02;
    float id  = 1.0f / det;
    float inv[3][3];
    inv[0][0] = c00 * id;
    inv[0][1] = (Bm[0][2]*Bm[2][1] - Bm[0][1]*Bm[2][2]) * id;
    inv[0][2] = (Bm[0][1]*Bm[1][2] - Bm[0][2]*Bm[1][1]) * id;
    inv[1][0] = c01 * id;
    inv[1][1] = (Bm[0][0]*Bm[2][2] - Bm[0][2]*Bm[2][0]) * id;
    inv[1][2] = (Bm[0][2]*Bm[1][0] - Bm[0][0]*Bm[1][2]) * id;
    inv[2][0] = c02 * id;
    inv[2][1] = (Bm[0][1]*Bm[2][0] - Bm[0][0]*Bm[2][1]) * id;
    inv[2][2] = (Bm[0][0]*Bm[1][1] - Bm[0][1]*Bm[1][0]) * id;

#pragma unroll
    for (int x = 0; x < NX; x++) {
        g_s[x][i] = sv[x];
#pragma unroll
        for (int p = 0; p < NX; p++) g_Binv[x*NX + p][i] = inv[x][p];
    }

    // Initial guess: F0 = Binv * s  (zeroth-order solution, saves one sweep)
#pragma unroll
    for (int x = 0; x < NX; x++) {
        float f = inv[x][0]*sv[0] + inv[x][1]*sv[1] + inv[x][2]*sv[2];
        g_F[0][x][i]  = f;
        g_wF[0][x][i] = ci * f;
    }
}

// ---------------------------------------------------------------------------
// One Jacobi sweep: for each row i<NE-1 (one warp per row),
//   y[x] = sum_{p, j=i+1..NE-2} K[x][p][i][j] * wF[p][j]
//   F_new[:,i] = Binv_i * (s[:,i] + y)
// Triangular imbalance handled by pairing low/high rows within each block.
// ---------------------------------------------------------------------------
__global__ __launch_bounds__(256) void iter_kernel(
    const float* __restrict__ K, int src, int dst)
{
    int g    = (blockIdx.x * blockDim.x + threadIdx.x) >> 5;
    int lane = threadIdx.x & 31;
    if (g >= NE-1) return;
    // balance: even g -> low rows, odd g -> high rows
    int i = (g & 1) ? (NE-2 - (g >> 1)) : (g >> 1);

    const float* __restrict__ wf0 = g_wF[src][0];
    const float* __restrict__ wf1 = g_wF[src][1];
    const float* __restrict__ wf2 = g_wF[src][2];

    const float* __restrict__ k00 = K + ((size_t)((0*NX+0)*NE + i))*NE;
    const float* __restrict__ k01 = K + ((size_t)((0*NX+1)*NE + i))*NE;
    const float* __restrict__ k02 = K + ((size_t)((0*NX+2)*NE + i))*NE;
    const float* __restrict__ k10 = K + ((size_t)((1*NX+0)*NE + i))*NE;
    const float* __restrict__ k11 = K + ((size_t)((1*NX+1)*NE + i))*NE;
    const float* __restrict__ k12 = K + ((size_t)((1*NX+2)*NE + i))*NE;
    const float* __restrict__ k20 = K + ((size_t)((2*NX+0)*NE + i))*NE;
    const float* __restrict__ k21 = K + ((size_t)((2*NX+1)*NE + i))*NE;
    const float* __restrict__ k22 = K + ((size_t)((2*NX+2)*NE + i))*NE;

    float4 a0 = make_float4(0,0,0,0);
    float4 a1 = make_float4(0,0,0,0);
    float4 a2 = make_float4(0,0,0,0);

    int jv  = (i + 1) & ~3;        // 16B-aligned start; wF[NE-1]==0 guards the tail
    int jb0 = jv + 4*lane;

#define ACCUM(JB, W0, W1, W2)                                                  \
    do {                                                                       \
        float4 kk;                                                             \
        kk = ld4(k00, JB); a0.x += kk.x*W0.x; a0.y += kk.y*W0.y;               \
                           a0.z += kk.z*W0.z; a0.w += kk.w*W0.w;               \
        kk = ld4(k01, JB); a0.x += kk.x*W1.x; a0.y += kk.y*W1.y;               \
                           a0.z += kk.z*W1.z; a0.w += kk.w*W1.w;               \
        kk = ld4(k02, JB); a0.x += kk.x*W2.x; a0.y += kk.y*W2.y;               \
                           a0.z += kk.z*W2.z; a0.w += kk.w*W2.w;               \
        kk = ld4(k10, JB); a1.x += kk.x*W0.x; a1.y += kk.y*W0.y;               \
                           a1.z += kk.z*W0.z; a1.w += kk.w*W0.w;               \
        kk = ld4(k11, JB); a1.x += kk.x*W1.x; a1.y += kk.y*W1.y;               \
                           a1.z += kk.z*W1.z; a1.w += kk.w*W1.w;               \
        kk = ld4(k12, JB); a1.x += kk.x*W2.x; a1.y += kk.y*W2.y;               \
                           a1.z += kk.z*W2.z; a1.w += kk.w*W2.w;               \
        kk = ld4(k20, JB); a2.x += kk.x*W0.x; a2.y += kk.y*W0.y;               \
                           a2.z += kk.z*W0.z; a2.w += kk.w*W0.w;               \
        kk = ld4(k21, JB); a2.x += kk.x*W1.x; a2.y += kk.y*W1.y;               \
                           a2.z += kk.z*W1.z; a2.w += kk.w*W1.w;               \
        kk = ld4(k22, JB); a2.x += kk.x*W2.x; a2.y += kk.y*W2.y;               \
                           a2.z += kk.z*W2.z; a2.w += kk.w*W2.w;               \
    } while (0)

    int jb = jb0;
    if (jb < NE) {
        // peeled first block: mask elements with j <= i (only lane 0 can hit)
        float4 w0 = ld4(wf0, jb), w1 = ld4(wf1, jb), w2 = ld4(wf2, jb);
        if (jb + 0 <= i) { w0.x = 0.f; w1.x = 0.f; w2.x = 0.f; }
        if (jb + 1 <= i) { w0.y = 0.f; w1.y = 0.f; w2.y = 0.f; }
        if (jb + 2 <= i) { w0.z = 0.f; w1.z = 0.f; w2.z = 0.f; }
        if (jb + 3 <= i) { w0.w = 0.f; w1.w = 0.f; w2.w = 0.f; }
        ACCUM(jb, w0, w1, w2);
        jb += 128;
    }
#pragma unroll 2
    for (; jb < NE; jb += 128) {
        float4 w0 = ld4(wf0, jb), w1 = ld4(wf1, jb), w2 = ld4(wf2, jb);
        ACCUM(jb, w0, w1, w2);
    }
#undef ACCUM

    float y0 = (a0.x + a0.y) + (a0.z + a0.w);
    float y1 = (a1.x + a1.y) + (a1.z + a1.w);
    float y2 = (a2.x + a2.y) + (a2.z + a2.w);
#pragma unroll
    for (int o = 16; o > 0; o >>= 1) {
        y0 += __shfl_xor_sync(0xffffffffu, y0, o);
        y1 += __shfl_xor_sync(0xffffffffu, y1, o);
        y2 += __shfl_xor_sync(0xffffffffu, y2, o);
    }

    if (lane == 0) {
        float s0 = g_s[0][i] + y0;
        float s1 = g_s[1][i] + y1;
        float s2 = g_s[2][i] + y2;
        float f0 = g_Binv[0][i]*s0 + g_Binv[1][i]*s1 + g_Binv[2][i]*s2;
        float f1 = g_Binv[3][i]*s0 + g_Binv[4][i]*s1 + g_Binv[5][i]*s2;
        float f2 = g_Binv[6][i]*s0 + g_Binv[7][i]*s1 + g_Binv[8][i]*s2;
        float ci = g_c[i];
        g_F[dst][0][i]  = f0;  g_wF[dst][0][i] = ci * f0;
        g_F[dst][1][i]  = f1;  g_wF[dst][1][i] = ci * f1;
        g_F[dst][2][i]  = f2;  g_wF[dst][2][i] = ci * f2;
    }
}

// ---------------------------------------------------------------------------
// Finalize: out[0,:] = E_grid; out[1+x,:] = max(F,0)  (mirrors where(F>~0,F,~0),
// since approx_zero = float32(1e-200) == 0)
// ---------------------------------------------------------------------------
__global__ __launch_bounds__(256) void final_kernel(
    const float* __restrict__ E, float* __restrict__ out, int src)
{
    int i = blockIdx.x * blockDim.x + threadIdx.x;
    if (i >= NE) return;
    out[i] = E[i];
#pragma unroll
    for (int x = 0; x < NX; x++) {
        float f = g_F[src][x][i];
        out[(x + 1) * NE + i] = (f > 0.0f) ? f : 0.0f;
    }
}

extern "C" void kernel_launch(void* const* d_in, const int* in_sizes, int n_in,
                              void* d_out, int out_size)
{
    const float* E  = (const float*)d_in[0];
    const float* R  = (const float*)d_in[1];
    const float* K  = (const float*)d_in[2];
    const float* S0 = (const float*)d_in[3];
    const float* SC = (const float*)d_in[4];
    float* out = (float*)d_out;

    setup_kernel<<<(NE + 255) / 256, 256>>>(E, R, K, S0, SC);

    int src = 0;
    // one warp per row: NE-1 rows -> 2047 warps -> 256 blocks x 8 warps
    for (int it = 0; it < NITER; it++) {
        iter_kernel<<<256, 256>>>(K, src, 1 - src);
        src = 1 - src;
    }

    final_kernel<<<(NE + 255) / 256, 256>>>(E, out, src);
}

// round 3
// speedup vs baseline: 2.9137x; 2.9137x over previous
#include <cuda_runtime.h>
#include <math.h>

#define NE 2048
#define NX 3
#define NITER 7

// Scratch (allocation-free): all __device__ globals.
__device__ float g_s[NX][NE];        // static RHS (SC + last-column terms)
__device__ float g_Binv[NX*NX][NE];  // per-bin 3x3 inverse of B_i
__device__ float g_c[NE];            // c_j = dy*E_j
__device__ float g_F[2][NX][NE];     // double-buffered solution
__device__ float g_wF[2][NX][NE];    // double-buffered c_j*F_j (col NE-1 forced 0)

__device__ __forceinline__ float4 ld4(const float* __restrict__ p, int j) {
    return *reinterpret_cast<const float4*>(p + j);
}

// ---------------------------------------------------------------------------
// Setup: dy, src_last, F[:,NE-1], c_j, B_i^{-1}, s, initial guess F0 = Binv*s
// ---------------------------------------------------------------------------
__global__ __launch_bounds__(256) void setup_kernel(
    const float* __restrict__ E, const float* __restrict__ R,
    const float* __restrict__ K, const float* __restrict__ S0,
    const float* __restrict__ SC)
{
    int i = blockIdx.x * blockDim.x + threadIdx.x;
    if (i >= NE) return;

    const float dy = logf(E[NE-1] / E[0]) / (float)(NE - 1);

    float srcl[NX];
#pragma unroll
    for (int p = 0; p < NX; p++) srcl[p] = S0[p] / R[p*NE + NE-1];

    float Flast[NX];
#pragma unroll
    for (int x = 0; x < NX; x++) {
        float acc = SC[x*NE + NE-1];
#pragma unroll
        for (int p = 0; p < NX; p++)
            acc += K[((size_t)((x*NX + p)*NE + (NE-1)))*NE + (NE-1)] * srcl[p];
        Flast[x] = acc / R[x*NE + NE-1];
    }

    if (i == NE-1) {
        g_c[NE-1] = dy * E[NE-1];
#pragma unroll
        for (int x = 0; x < NX; x++) {
            g_F[0][x][NE-1] = Flast[x];
            g_F[1][x][NE-1] = Flast[x];
            g_wF[0][x][NE-1] = 0.0f;   // j=NE-1 handled inside s, never in matvec
            g_wF[1][x][NE-1] = 0.0f;
        }
        return;
    }

    const float ci = dy * E[i];
    g_c[i] = ci;
    const float w_last = 0.5f * dy * E[NE-1];

    float Bm[3][3];
    float sv[NX];
#pragma unroll
    for (int x = 0; x < NX; x++) {
        float acc = SC[x*NE + i];
#pragma unroll
        for (int p = 0; p < NX; p++) {
            size_t rb = ((size_t)((x*NX + p)*NE + i)) * NE;
            float Kii = K[rb + i];
            float Kil = K[rb + NE-1];
            Bm[x][p] = -0.5f * ci * Kii + ((x == p) ? R[x*NE + i] : 0.0f);
            acc += Kil * (w_last * Flast[p] + srcl[p]);
        }
        sv[x] = acc;
    }

    // 3x3 inverse (adjugate / det); B ~ diag(R) dominant -> well-conditioned
    float c00 = Bm[1][1]*Bm[2][2] - Bm[1][2]*Bm[2][1];
    float c01 = Bm[1][2]*Bm[2][0] - Bm[1][0]*Bm[2][2];
    float c02 = Bm[1][0]*Bm[2][1] - Bm[1][1]*Bm[2][0];
    float det = Bm[0][0]*c00 + Bm[0][1]*c01 + Bm[0][2]*c02;
    float id  = 1.0f / det;
    float inv[3][3];
    inv[0][0] = c00 * id;
    inv[0][1] = (Bm[0][2]*Bm[2][1] - Bm[0][1]*Bm[2][2]) * id;
    inv[0][2] = (Bm[0][1]*Bm[1][2] - Bm[0][2]*Bm[1][1]) * id;
    inv[1][0] = c01 * id;
    inv[1][1] = (Bm[0][0]*Bm[2][2] - Bm[0][2]*Bm[2][0]) * id;
    inv[1][2] = (Bm[0][2]*Bm[1][0] - Bm[0][0]*Bm[1][2]) * id;
    inv[2][0] = c02 * id;
    inv[2][1] = (Bm[0][1]*Bm[2][0] - Bm[0][0]*Bm[2][1]) * id;
    inv[2][2] = (Bm[0][0]*Bm[1][1] - Bm[0][1]*Bm[1][0]) * id;

#pragma unroll
    for (int x = 0; x < NX; x++) {
        g_s[x][i] = sv[x];
#pragma unroll
        for (int p = 0; p < NX; p++) g_Binv[x*NX + p][i] = inv[x][p];
    }

    // Initial guess: F0 = Binv * s
#pragma unroll
    for (int x = 0; x < NX; x++) {
        float f = inv[x][0]*sv[0] + inv[x][1]*sv[1] + inv[x][2]*sv[2];
        g_F[0][x][i]  = f;
        g_wF[0][x][i] = ci * f;
    }
}

// ---------------------------------------------------------------------------
// One Jacobi sweep, block-per-row-pair:
// block b handles rows r0=b and r1=NE-2-b (constant total work per block).
// 256 threads cooperatively reduce y[x] = sum_{p,j>i} K[x][p][i][j]*wF[p][j],
// then thread 0 applies Binv_i and writes F/wF.
// ---------------------------------------------------------------------------
__device__ __forceinline__ void process_row(
    int i, const float* __restrict__ K, int src, int dst,
    float red[3][8], int tid, int lane, int warp)
{
    const float* __restrict__ wf0 = g_wF[src][0];
    const float* __restrict__ wf1 = g_wF[src][1];
    const float* __restrict__ wf2 = g_wF[src][2];

    const float* __restrict__ k00 = K + ((size_t)((0*NX+0)*NE + i))*NE;
    const float* __restrict__ k01 = K + ((size_t)((0*NX+1)*NE + i))*NE;
    const float* __restrict__ k02 = K + ((size_t)((0*NX+2)*NE + i))*NE;
    const float* __restrict__ k10 = K + ((size_t)((1*NX+0)*NE + i))*NE;
    const float* __restrict__ k11 = K + ((size_t)((1*NX+1)*NE + i))*NE;
    const float* __restrict__ k12 = K + ((size_t)((1*NX+2)*NE + i))*NE;
    const float* __restrict__ k20 = K + ((size_t)((2*NX+0)*NE + i))*NE;
    const float* __restrict__ k21 = K + ((size_t)((2*NX+1)*NE + i))*NE;
    const float* __restrict__ k22 = K + ((size_t)((2*NX+2)*NE + i))*NE;

    float y0 = 0.f, y1 = 0.f, y2 = 0.f;

    int jv  = (i + 1) & ~3;          // 16B-aligned start; wF[NE-1]==0 sentinel
    int jb  = jv + 4 * tid;          // pass 0 offset for this thread

#define ACCUM(JB, W0, W1, W2)                                                  \
    do {                                                                       \
        float4 kk;                                                             \
        kk = ld4(k00, JB); y0 += kk.x*W0.x + kk.y*W0.y + kk.z*W0.z + kk.w*W0.w;\
        kk = ld4(k01, JB); y0 += kk.x*W1.x + kk.y*W1.y + kk.z*W1.z + kk.w*W1.w;\
        kk = ld4(k02, JB); y0 += kk.x*W2.x + kk.y*W2.y + kk.z*W2.z + kk.w*W2.w;\
        kk = ld4(k10, JB); y1 += kk.x*W0.x + kk.y*W0.y + kk.z*W0.z + kk.w*W0.w;\
        kk = ld4(k11, JB); y1 += kk.x*W1.x + kk.y*W1.y + kk.z*W1.z + kk.w*W1.w;\
        kk = ld4(k12, JB); y1 += kk.x*W2.x + kk.y*W2.y + kk.z*W2.z + kk.w*W2.w;\
        kk = ld4(k20, JB); y2 += kk.x*W0.x + kk.y*W0.y + kk.z*W0.z + kk.w*W0.w;\
        kk = ld4(k21, JB); y2 += kk.x*W1.x + kk.y*W1.y + kk.z*W1.z + kk.w*W1.w;\
        kk = ld4(k22, JB); y2 += kk.x*W2.x + kk.y*W2.y + kk.z*W2.z + kk.w*W2.w;\
    } while (0)

    if (jb < NE) {
        // pass 0: mask elements with j <= i (can only occur in this pass)
        float4 w0 = ld4(wf0, jb), w1 = ld4(wf1, jb), w2 = ld4(wf2, jb);
        if (jb + 0 <= i) { w0.x = 0.f; w1.x = 0.f; w2.x = 0.f; }
        if (jb + 1 <= i) { w0.y = 0.f; w1.y = 0.f; w2.y = 0.f; }
        if (jb + 2 <= i) { w0.z = 0.f; w1.z = 0.f; w2.z = 0.f; }
        if (jb + 3 <= i) { w0.w = 0.f; w1.w = 0.f; w2.w = 0.f; }
        ACCUM(jb, w0, w1, w2);
        jb += 4 * 256;
    }
    for (; jb < NE; jb += 4 * 256) {
        float4 w0 = ld4(wf0, jb), w1 = ld4(wf1, jb), w2 = ld4(wf2, jb);
        ACCUM(jb, w0, w1, w2);
    }
#undef ACCUM

    // warp reduce
#pragma unroll
    for (int o = 16; o > 0; o >>= 1) {
        y0 += __shfl_xor_sync(0xffffffffu, y0, o);
        y1 += __shfl_xor_sync(0xffffffffu, y1, o);
        y2 += __shfl_xor_sync(0xffffffffu, y2, o);
    }
    if (lane == 0) { red[0][warp] = y0; red[1][warp] = y1; red[2][warp] = y2; }
    __syncthreads();

    if (tid == 0) {
        float s0 = g_s[0][i], s1 = g_s[1][i], s2 = g_s[2][i];
#pragma unroll
        for (int w = 0; w < 8; w++) {
            s0 += red[0][w]; s1 += red[1][w]; s2 += red[2][w];
        }
        float f0 = g_Binv[0][i]*s0 + g_Binv[1][i]*s1 + g_Binv[2][i]*s2;
        float f1 = g_Binv[3][i]*s0 + g_Binv[4][i]*s1 + g_Binv[5][i]*s2;
        float f2 = g_Binv[6][i]*s0 + g_Binv[7][i]*s1 + g_Binv[8][i]*s2;
        float ci = g_c[i];
        g_F[dst][0][i]  = f0;  g_wF[dst][0][i] = ci * f0;
        g_F[dst][1][i]  = f1;  g_wF[dst][1][i] = ci * f1;
        g_F[dst][2][i]  = f2;  g_wF[dst][2][i] = ci * f2;
    }
    __syncthreads();   // smem reuse guard for second row
}

__global__ __launch_bounds__(256) void iter_kernel(
    const float* __restrict__ K, int src, int dst)
{
    __shared__ float red[3][8];
    int tid  = threadIdx.x;
    int lane = tid & 31;
    int warp = tid >> 5;
    int b    = blockIdx.x;           // 0..1023

    int r0 = b;                      // short j-range grows as b increases
    int r1 = NE - 2 - b;             // complementary row

    process_row(r0, K, src, dst, red, tid, lane, warp);
    if (r1 != r0)
        process_row(r1, K, src, dst, red, tid, lane, warp);
}

// ---------------------------------------------------------------------------
// Finalize: out[0,:] = E_grid; out[1+x,:] = max(F,0)
// ---------------------------------------------------------------------------
__global__ __launch_bounds__(256) void final_kernel(
    const float* __restrict__ E, float* __restrict__ out, int src)
{
    int i = blockIdx.x * blockDim.x + threadIdx.x;
    if (i >= NE) return;
    out[i] = E[i];
#pragma unroll
    for (int x = 0; x < NX; x++) {
        float f = g_F[src][x][i];
        out[(x + 1) * NE + i] = (f > 0.0f) ? f : 0.0f;
    }
}

extern "C" void kernel_launch(void* const* d_in, const int* in_sizes, int n_in,
                              void* d_out, int out_size)
{
    const float* E  = (const float*)d_in[0];
    const float* R  = (const float*)d_in[1];
    const float* K  = (const float*)d_in[2];
    const float* S0 = (const float*)d_in[3];
    const float* SC = (const float*)d_in[4];
    float* out = (float*)d_out;

    setup_kernel<<<(NE + 255) / 256, 256>>>(E, R, K, S0, SC);

    int src = 0;
    for (int it = 0; it < NITER; it++) {
        iter_kernel<<<NE/2, 256>>>(K, src, 1 - src);
        src = 1 - src;
    }

    final_kernel<<<(NE + 255) / 256, 256>>>(E, out, src);
}